// round 7
// baseline (speedup 1.0000x reference)
#include <cuda_runtime.h>
#include <cstdint>

// Problem shape (fixed): x:(32,512,64,64) f32, weight:(1,1,3,3), k=256
#define BB 32
#define NN 512
#define HH 64
#define WW 64
#define IMG_ELEMS (HH * WW)          // 4096
#define CHB 8                        // batches per chunk (67MB of x < 126MB L2)
#define NCHUNK (BB / CHB)            // 4
#define CHUNK_IMGS (CHB * NN)        // 4096 images per chunk

// Scratch (no cudaMalloc allowed)
__device__ float2 g_scores[BB * NN];
__device__ int    g_order[BB * NN];

// ---------------------------------------------------------------------------
// Phase 1: conv score, 2 images per warp. Lanes 0-15 -> image A, 16-31 -> B.
// Sub-lane q owns cols 4q..4q+3 (one LDG.128 per row, MLP=8 rows in flight =
// 4KB/warp). Horizontal neighbors via width-16 SHFL. Vertical 3-tap window
// in registers. Per-row Fast2Sum fold. block = 64 thr (2 warps, 4 images).
// ---------------------------------------------------------------------------
__global__ __launch_bounds__(64) void score_kernel(
    const float* __restrict__ x, const float* __restrict__ w,
    float2* __restrict__ scores)
{
    const int li  = threadIdx.x & 31;
    const int q   = li & 15;                        // sub-lane within image
    const int img = blockIdx.x * 4 + (threadIdx.x >> 5) * 2 + (li >> 4);
    const bool tq = (q == 15);                      // cols 62,63 invalid

    const float wc = w[0];   // corners
    const float wE = w[1];   // edges
    const float wm = w[4];   // center

    const float4* b4 = reinterpret_cast<const float4*>(
        x + (size_t)img * IMG_ELEMS) + q;           // 16 float4 per row

    // Sliding horizontal sums of the two previous rows (4 cols per lane)
    float Ha1[4], Hm1[4], Ha2[4], Hm2[4];
    float s = 0.f, e = 0.f;
    float4 v[8];

#define HROW(vv, HaO, HmO)                                                  \
    {                                                                       \
        float nx = __shfl_down_sync(0xffffffffu, (vv).x, 1, 16);            \
        float ny = __shfl_down_sync(0xffffffffu, (vv).y, 1, 16);            \
        HaO[0] = (vv).x + (vv).z;  HmO[0] = (vv).y;                         \
        HaO[1] = (vv).y + (vv).w;  HmO[1] = (vv).z;                         \
        HaO[2] = (vv).z + nx;      HmO[2] = (vv).w;                         \
        HaO[3] = (vv).w + ny;      HmO[3] = nx;                             \
    }

#define DO_ROW(vv)                                                          \
    {                                                                       \
        float Hac[4], Hmc[4];                                               \
        HROW(vv, Hac, Hmc);                                                 \
        float s1 = Ha2[0] + Hac[0];                                         \
        float s2 = (Hm2[0] + Hmc[0]) + Ha1[0];                              \
        float o0 = fmaf(wc, s1, fmaf(wE, s2, wm * Hm1[0]));                 \
        s1 = Ha2[1] + Hac[1];                                               \
        s2 = (Hm2[1] + Hmc[1]) + Ha1[1];                                    \
        float o1 = fmaf(wc, s1, fmaf(wE, s2, wm * Hm1[1]));                 \
        s1 = Ha2[2] + Hac[2];                                               \
        s2 = (Hm2[2] + Hmc[2]) + Ha1[2];                                    \
        float o2 = fmaf(wc, s1, fmaf(wE, s2, wm * Hm1[2]));                 \
        s1 = Ha2[3] + Hac[3];                                               \
        s2 = (Hm2[3] + Hmc[3]) + Ha1[3];                                    \
        float o3 = fmaf(wc, s1, fmaf(wE, s2, wm * Hm1[3]));                 \
        float r01 = fabsf(o0) + fabsf(o1);                                  \
        float r23 = fabsf(o2) + fabsf(o3);                                  \
        float row = tq ? r01 : (r01 + r23);                                 \
        float tt  = __fadd_rn(s, row);                                      \
        e = __fadd_rn(e, __fadd_rn(__fsub_rn(s, tt), row));                 \
        s = tt;                                                             \
        Ha2[0] = Ha1[0]; Hm2[0] = Hm1[0]; Ha1[0] = Hac[0]; Hm1[0] = Hmc[0]; \
        Ha2[1] = Ha1[1]; Hm2[1] = Hm1[1]; Ha1[1] = Hac[1]; Hm1[1] = Hmc[1]; \
        Ha2[2] = Ha1[2]; Hm2[2] = Hm1[2]; Ha1[2] = Hac[2]; Hm1[2] = Hmc[2]; \
        Ha2[3] = Ha1[3]; Hm2[3] = Hm1[3]; Ha1[3] = Hac[3]; Hm1[3] = Hmc[3]; \
    }

    // ---- chunk 0: rows 0..7 (prime with rows 0,1; compute rows 2..7) ----
#pragma unroll
    for (int i = 0; i < 8; i++) v[i] = b4[i * 16];
    HROW(v[0], Ha2, Hm2);
    HROW(v[1], Ha1, Hm1);
#pragma unroll
    for (int i = 2; i < 8; i++) DO_ROW(v[i]);

    // ---- chunks 1..7 ----
    for (int c = 1; c < 8; c++) {
#pragma unroll
        for (int i = 0; i < 8; i++) v[i] = b4[(c * 8 + i) * 16];
#pragma unroll
        for (int i = 0; i < 8; i++) DO_ROW(v[i]);
    }
#undef DO_ROW
#undef HROW

    // Reduction within each 16-lane half (exact TwoSum double-float)
#pragma unroll
    for (int off = 8; off; off >>= 1) {
        float s2 = __shfl_down_sync(0xffffffffu, s, off, 16);
        float e2 = __shfl_down_sync(0xffffffffu, e, off, 16);
        float tt  = __fadd_rn(s, s2);
        float z   = __fsub_rn(tt, s);
        float err = __fadd_rn(__fsub_rn(s, __fsub_rn(tt, z)), __fsub_rn(s2, z));
        e = __fadd_rn(__fadd_rn(e, e2), err);
        s = tt;
    }

    if (q == 0) {
        float h = __fadd_rn(s, e);
        float l = __fadd_rn(__fsub_rn(s, h), e);
        scores[img] = make_float2(h, l);
    }
}

// ---------------------------------------------------------------------------
// Phase 2: exact top-k ranking per batch (descending, ties -> lower index first)
// ---------------------------------------------------------------------------
__global__ __launch_bounds__(NN) void topk_kernel(
    const float2* __restrict__ scores, int* __restrict__ order, int k)
{
    __shared__ float2 sc[NN];
    const int b = blockIdx.x;
    const int n = threadIdx.x;
    sc[n] = scores[b * NN + n];
    __syncthreads();

    const float2 mine = sc[n];
    int rank = 0;
#pragma unroll 8
    for (int m = 0; m < NN; m++) {
        float2 o = sc[m];
        bool better = (o.x > mine.x) ||
                      (o.x == mine.x && (o.y > mine.y ||
                                         (o.y == mine.y && m < n)));
        rank += better;
    }
    if (rank < k) order[b * k + rank] = n;
}

// ---------------------------------------------------------------------------
// Phase 3: gather, 2 images per 256-thread block. Runs right after its
// chunk's score kernel, so the source images are L2-resident.
// ---------------------------------------------------------------------------
__global__ __launch_bounds__(256) void gather_kernel(
    const float* __restrict__ x, const int* __restrict__ order,
    float* __restrict__ out, int k, int base_pair)
{
    const int pair = base_pair + blockIdx.x;
    const int bj0  = pair * 2;
    const int bj1  = bj0 + 1;
    const int n0   = __ldg(&order[bj0]);
    const int n1   = __ldg(&order[bj1]);
    const int b    = bj0 / k;                      // bj0,bj1 same batch (k even)

    const float4* s0 = reinterpret_cast<const float4*>(
        x + ((size_t)(b * NN + n0)) * IMG_ELEMS);
    const float4* s1 = reinterpret_cast<const float4*>(
        x + ((size_t)(b * NN + n1)) * IMG_ELEMS);
    float4* d0 = reinterpret_cast<float4*>(out + (size_t)bj0 * IMG_ELEMS);
    float4* d1 = reinterpret_cast<float4*>(out + (size_t)bj1 * IMG_ELEMS);

    float4 r0[4], r1[4];
#pragma unroll
    for (int i = 0; i < 4; i++) r0[i] = s0[threadIdx.x + i * 256];
#pragma unroll
    for (int i = 0; i < 4; i++) r1[i] = s1[threadIdx.x + i * 256];
#pragma unroll
    for (int i = 0; i < 4; i++) d0[threadIdx.x + i * 256] = r0[i];
#pragma unroll
    for (int i = 0; i < 4; i++) d1[threadIdx.x + i * 256] = r1[i];
}

// ---------------------------------------------------------------------------
// Chunked pipeline: for each group of 8 batches, score -> topk -> gather.
// The chunk's x slice (67MB) stays L2-resident, so gather reads hit L2.
// ---------------------------------------------------------------------------
extern "C" void kernel_launch(void* const* d_in, const int* in_sizes, int n_in,
                              void* d_out, int out_size)
{
    const float* x = (const float*)d_in[0];
    const float* w = (const float*)d_in[1];
    float* out = (float*)d_out;

    const int k = out_size / (BB * IMG_ELEMS);   // = 256

    for (int c = 0; c < NCHUNK; c++) {
        score_kernel<<<CHUNK_IMGS / 4, 64>>>(
            x + (size_t)c * CHUNK_IMGS * IMG_ELEMS, w,
            g_scores + c * CHUNK_IMGS);
        topk_kernel<<<CHB, NN>>>(
            g_scores + c * CHUNK_IMGS, g_order + c * CHB * k, k);
        gather_kernel<<<(CHB * k) / 2, 256>>>(
            x, g_order, out, k, c * (CHB * k) / 2);
    }
}

// round 8
// speedup vs baseline: 1.8856x; 1.8856x over previous
#include <cuda_runtime.h>
#include <cstdint>

// Problem shape (fixed): x:(32,512,64,64) f32, weight:(1,1,3,3), k=256
#define BB 32
#define NN 512
#define HH 64
#define WW 64
#define IMG_ELEMS (HH * WW)          // 4096

// Scratch (no cudaMalloc allowed)
__device__ float2 g_scores[BB * NN];
__device__ int    g_order[BB * NN];

// ---------------------------------------------------------------------------
// Phase 1 (R4/R6 known-good): warp-per-image conv score. Lane li owns cols
// 2li,2li+1. Rows in chunks of 8: all 8 LDG.64 issued before compute (MLP=8).
// Horizontal neighbors via SHFL; vertical 3-tap window in registers.
// grid = B*N/8, block = 256 (8 warps = 8 images).
// ---------------------------------------------------------------------------
__global__ __launch_bounds__(256) void score_kernel(
    const float* __restrict__ x, const float* __restrict__ w,
    float2* __restrict__ scores)
{
    const int li   = threadIdx.x & 31;
    const int img  = blockIdx.x * 8 + (threadIdx.x >> 5);
    const bool tail = (li == 31);                 // cols 62,63: invalid outputs

    const float wc = w[0];   // corners
    const float wE = w[1];   // edges
    const float wm = w[4];   // center

    const float2* b2 = reinterpret_cast<const float2*>(
        x + (size_t)img * IMG_ELEMS) + li;        // 32 float2 per row

    float Ha1[2], Hm1[2], Ha2[2], Hm2[2];
    float s = 0.f, e = 0.f;

    float2 v[8];

    // ---- chunk 0: rows 0..7 (prime with rows 0,1; compute rows 2..7) ----
#pragma unroll
    for (int i = 0; i < 8; i++) v[i] = b2[i * 32];

    {
        float nx = __shfl_down_sync(0xffffffffu, v[0].x, 1);
        float ny = __shfl_down_sync(0xffffffffu, v[0].y, 1);
        Ha2[0] = v[0].x + nx;  Hm2[0] = v[0].y;
        Ha2[1] = v[0].y + ny;  Hm2[1] = nx;
        nx = __shfl_down_sync(0xffffffffu, v[1].x, 1);
        ny = __shfl_down_sync(0xffffffffu, v[1].y, 1);
        Ha1[0] = v[1].x + nx;  Hm1[0] = v[1].y;
        Ha1[1] = v[1].y + ny;  Hm1[1] = nx;
    }

#define DO_ROW(vv)                                                          \
    {                                                                       \
        float nx = __shfl_down_sync(0xffffffffu, (vv).x, 1);                \
        float ny = __shfl_down_sync(0xffffffffu, (vv).y, 1);                \
        float Hac0 = (vv).x + nx, Hmc0 = (vv).y;                            \
        float Hac1 = (vv).y + ny, Hmc1 = nx;                                \
        float s1a = Ha2[0] + Hac0;                                          \
        float s2a = (Hm2[0] + Hmc0) + Ha1[0];                               \
        float vra = fmaf(wc, s1a, fmaf(wE, s2a, wm * Hm1[0]));              \
        float s1b = Ha2[1] + Hac1;                                          \
        float s2b = (Hm2[1] + Hmc1) + Ha1[1];                               \
        float vrb = fmaf(wc, s1b, fmaf(wE, s2b, wm * Hm1[1]));              \
        float row = fabsf(vra) + fabsf(vrb);                                \
        if (tail) row = 0.f;                                                \
        float tt  = __fadd_rn(s, row);                                      \
        e = __fadd_rn(e, __fadd_rn(__fsub_rn(s, tt), row));                 \
        s = tt;                                                             \
        Ha2[0] = Ha1[0]; Hm2[0] = Hm1[0]; Ha1[0] = Hac0; Hm1[0] = Hmc0;     \
        Ha2[1] = Ha1[1]; Hm2[1] = Hm1[1]; Ha1[1] = Hac1; Hm1[1] = Hmc1;     \
    }

#pragma unroll
    for (int i = 2; i < 8; i++) DO_ROW(v[i]);

    // ---- chunks 1..7 ----
    for (int c = 1; c < 8; c++) {
#pragma unroll
        for (int i = 0; i < 8; i++) v[i] = b2[(c * 8 + i) * 32];
#pragma unroll
        for (int i = 0; i < 8; i++) DO_ROW(v[i]);
    }
#undef DO_ROW

    // Full-warp double-float reduction (exact TwoSum)
#pragma unroll
    for (int off = 16; off; off >>= 1) {
        float s2 = __shfl_down_sync(0xffffffffu, s, off);
        float e2 = __shfl_down_sync(0xffffffffu, e, off);
        float tt  = __fadd_rn(s, s2);
        float z   = __fsub_rn(tt, s);
        float err = __fadd_rn(__fsub_rn(s, __fsub_rn(tt, z)), __fsub_rn(s2, z));
        e = __fadd_rn(__fadd_rn(e, e2), err);
        s = tt;
    }

    if (li == 0) {
        float h = __fadd_rn(s, e);
        float l = __fadd_rn(__fsub_rn(s, h), e);
        scores[img] = make_float2(h, l);
    }
}

// ---------------------------------------------------------------------------
// Phase 2: exact top-k ranking per batch (descending, ties -> lower index first)
// ---------------------------------------------------------------------------
__global__ __launch_bounds__(NN) void topk_kernel(
    const float2* __restrict__ scores, int* __restrict__ order, int k)
{
    __shared__ float2 sc[NN];
    const int b = blockIdx.x;
    const int n = threadIdx.x;
    sc[n] = scores[b * NN + n];
    __syncthreads();

    const float2 mine = sc[n];
    int rank = 0;
#pragma unroll 8
    for (int m = 0; m < NN; m++) {
        float2 o = sc[m];
        bool better = (o.x > mine.x) ||
                      (o.x == mine.x && (o.y > mine.y ||
                                         (o.y == mine.y && m < n)));
        rank += better;
    }
    if (rank < k) order[b * k + rank] = n;
}

// ---------------------------------------------------------------------------
// Phase 3: gather, 4 images per 256-thread block. ONE int4 index load per
// block (amortized latency prefix), then a 2-stage software pipeline:
//   load i0,i1 -> store i0 | load i2 -> store i1 | load i3 -> store i2,i3
// so loads and stores overlap through the block's whole lifetime.
// grid = B*k/4 blocks, reversed order for possible L2 tail hits.
// ---------------------------------------------------------------------------
__global__ __launch_bounds__(256) void gather_kernel(
    const float* __restrict__ x, const int* __restrict__ order,
    float* __restrict__ out, int k)
{
    const int g   = gridDim.x - 1 - blockIdx.x;   // reversed for L2 reuse
    const int bj  = g * 4;                        // 4 consecutive outputs
    const int b   = bj / k;                       // same batch (k % 4 == 0)
    const int t   = threadIdx.x;

    const int4 nn = *reinterpret_cast<const int4*>(order + bj);
    const size_t ibase = (size_t)b * NN;

    const float4* s0 = reinterpret_cast<const float4*>(
        x + (ibase + nn.x) * IMG_ELEMS);
    const float4* s1 = reinterpret_cast<const float4*>(
        x + (ibase + nn.y) * IMG_ELEMS);
    const float4* s2 = reinterpret_cast<const float4*>(
        x + (ibase + nn.z) * IMG_ELEMS);
    const float4* s3 = reinterpret_cast<const float4*>(
        x + (ibase + nn.w) * IMG_ELEMS);
    float4* d = reinterpret_cast<float4*>(out + (size_t)bj * IMG_ELEMS);

    float4 ra[4], rb[4];
    // stage A: img0 + img1 loads in flight (8 x LDG.128 per thread-pair set)
#pragma unroll
    for (int i = 0; i < 4; i++) ra[i] = s0[t + i * 256];
#pragma unroll
    for (int i = 0; i < 4; i++) rb[i] = s1[t + i * 256];
    // store img0 while img2 loads
#pragma unroll
    for (int i = 0; i < 4; i++) d[t + i * 256] = ra[i];
#pragma unroll
    for (int i = 0; i < 4; i++) ra[i] = s2[t + i * 256];
    // store img1 while img3 loads
#pragma unroll
    for (int i = 0; i < 4; i++) d[1024 + t + i * 256] = rb[i];
#pragma unroll
    for (int i = 0; i < 4; i++) rb[i] = s3[t + i * 256];
    // drain
#pragma unroll
    for (int i = 0; i < 4; i++) d[2048 + t + i * 256] = ra[i];
#pragma unroll
    for (int i = 0; i < 4; i++) d[3072 + t + i * 256] = rb[i];
}

// ---------------------------------------------------------------------------
extern "C" void kernel_launch(void* const* d_in, const int* in_sizes, int n_in,
                              void* d_out, int out_size)
{
    const float* x = (const float*)d_in[0];
    const float* w = (const float*)d_in[1];
    float* out = (float*)d_out;

    const int k = out_size / (BB * IMG_ELEMS);   // = 256

    score_kernel<<<(BB * NN) / 8, 256>>>(x, w, g_scores);
    topk_kernel<<<BB, NN>>>(g_scores, g_order, k);
    gather_kernel<<<(BB * k) / 4, 256>>>(x, g_order, out, k);
}

// round 9
// speedup vs baseline: 2.0305x; 1.0769x over previous
#include <cuda_runtime.h>
#include <cstdint>

// Problem shape (fixed): x:(32,512,64,64) f32, weight:(1,1,3,3), k=256
#define BB 32
#define NN 512
#define HH 64
#define WW 64
#define IMG_ELEMS (HH * WW)          // 4096
#define IMG_BYTES (IMG_ELEMS * 4)    // 16384

// Scratch (no cudaMalloc allowed)
__device__ float2 g_scores[BB * NN];
__device__ int    g_order[BB * NN];

// ---------------------------------------------------------------------------
// Phase 1 (known-good R4/R6): warp-per-image conv score. Lane li owns cols
// 2li,2li+1. Rows in chunks of 8: all 8 LDG.64 issued before compute (MLP=8).
// ---------------------------------------------------------------------------
__global__ __launch_bounds__(256) void score_kernel(
    const float* __restrict__ x, const float* __restrict__ w,
    float2* __restrict__ scores)
{
    const int li   = threadIdx.x & 31;
    const int img  = blockIdx.x * 8 + (threadIdx.x >> 5);
    const bool tail = (li == 31);                 // cols 62,63: invalid outputs

    const float wc = w[0];   // corners
    const float wE = w[1];   // edges
    const float wm = w[4];   // center

    const float2* b2 = reinterpret_cast<const float2*>(
        x + (size_t)img * IMG_ELEMS) + li;        // 32 float2 per row

    float Ha1[2], Hm1[2], Ha2[2], Hm2[2];
    float s = 0.f, e = 0.f;

    float2 v[8];

#pragma unroll
    for (int i = 0; i < 8; i++) v[i] = b2[i * 32];

    {
        float nx = __shfl_down_sync(0xffffffffu, v[0].x, 1);
        float ny = __shfl_down_sync(0xffffffffu, v[0].y, 1);
        Ha2[0] = v[0].x + nx;  Hm2[0] = v[0].y;
        Ha2[1] = v[0].y + ny;  Hm2[1] = nx;
        nx = __shfl_down_sync(0xffffffffu, v[1].x, 1);
        ny = __shfl_down_sync(0xffffffffu, v[1].y, 1);
        Ha1[0] = v[1].x + nx;  Hm1[0] = v[1].y;
        Ha1[1] = v[1].y + ny;  Hm1[1] = nx;
    }

#define DO_ROW(vv)                                                          \
    {                                                                       \
        float nx = __shfl_down_sync(0xffffffffu, (vv).x, 1);                \
        float ny = __shfl_down_sync(0xffffffffu, (vv).y, 1);                \
        float Hac0 = (vv).x + nx, Hmc0 = (vv).y;                            \
        float Hac1 = (vv).y + ny, Hmc1 = nx;                                \
        float s1a = Ha2[0] + Hac0;                                          \
        float s2a = (Hm2[0] + Hmc0) + Ha1[0];                               \
        float vra = fmaf(wc, s1a, fmaf(wE, s2a, wm * Hm1[0]));              \
        float s1b = Ha2[1] + Hac1;                                          \
        float s2b = (Hm2[1] + Hmc1) + Ha1[1];                               \
        float vrb = fmaf(wc, s1b, fmaf(wE, s2b, wm * Hm1[1]));              \
        float row = fabsf(vra) + fabsf(vrb);                                \
        if (tail) row = 0.f;                                                \
        float tt  = __fadd_rn(s, row);                                      \
        e = __fadd_rn(e, __fadd_rn(__fsub_rn(s, tt), row));                 \
        s = tt;                                                             \
        Ha2[0] = Ha1[0]; Hm2[0] = Hm1[0]; Ha1[0] = Hac0; Hm1[0] = Hmc0;     \
        Ha2[1] = Ha1[1]; Hm2[1] = Hm1[1]; Ha1[1] = Hac1; Hm1[1] = Hmc1;     \
    }

#pragma unroll
    for (int i = 2; i < 8; i++) DO_ROW(v[i]);

    for (int c = 1; c < 8; c++) {
#pragma unroll
        for (int i = 0; i < 8; i++) v[i] = b2[(c * 8 + i) * 32];
#pragma unroll
        for (int i = 0; i < 8; i++) DO_ROW(v[i]);
    }
#undef DO_ROW

#pragma unroll
    for (int off = 16; off; off >>= 1) {
        float s2 = __shfl_down_sync(0xffffffffu, s, off);
        float e2 = __shfl_down_sync(0xffffffffu, e, off);
        float tt  = __fadd_rn(s, s2);
        float z   = __fsub_rn(tt, s);
        float err = __fadd_rn(__fsub_rn(s, __fsub_rn(tt, z)), __fsub_rn(s2, z));
        e = __fadd_rn(__fadd_rn(e, e2), err);
        s = tt;
    }

    if (li == 0) {
        float h = __fadd_rn(s, e);
        float l = __fadd_rn(__fsub_rn(s, h), e);
        scores[img] = make_float2(h, l);
    }
}

// ---------------------------------------------------------------------------
// Phase 2: top-k via sortable u64 keys. Value order (desc, tie: lower index)
// == u64 key order after sign-flip mapping of the renormalized (hi,lo) pair.
// ---------------------------------------------------------------------------
__device__ __forceinline__ uint32_t f2u_sortable(float f) {
    uint32_t u = __float_as_uint(f);
    return u ^ ((u & 0x80000000u) ? 0xFFFFFFFFu : 0x80000000u);
}

__global__ __launch_bounds__(NN) void topk_kernel(
    const float2* __restrict__ scores, int* __restrict__ order, int k)
{
    __shared__ unsigned long long sk[NN];
    const int b = blockIdx.x;
    const int n = threadIdx.x;
    float2 f = scores[b * NN + n];
    unsigned long long key =
        ((unsigned long long)f2u_sortable(f.x) << 32) | f2u_sortable(f.y);
    sk[n] = key;
    __syncthreads();

    int rank = 0;
#pragma unroll 8
    for (int m = 0; m < NN; m++) {
        unsigned long long o = sk[m];
        rank += (o > key) || (o == key && m < n);
    }
    if (rank < k) order[b * k + rank] = n;
}

// ---------------------------------------------------------------------------
// Phase 3: gather via async bulk copies (UBLKCP in, TMA bulk store out).
// One control thread per block, 6x16KB smem ring, 4 loads in flight.
// grid = 1024 blocks x 8 images. Dynamic smem = 6*16KB + barriers.
// ---------------------------------------------------------------------------
#define GS   6        // ring stages
#define GD   4        // prefetch depth (<= GS-2 for WAR safety)
#define GIPB 8        // images per block

__device__ __forceinline__ void mbar_wait(uint32_t mbar, uint32_t parity) {
    uint32_t done;
    do {
        asm volatile(
            "{\n\t.reg .pred p;\n\t"
            "mbarrier.try_wait.parity.shared.b64 p, [%1], %2;\n\t"
            "selp.b32 %0, 1, 0, p;\n\t}"
            : "=r"(done) : "r"(mbar), "r"(parity) : "memory");
    } while (!done);
}

__device__ __forceinline__ void bulk_load(uint32_t dst_smem, const void* src,
                                          uint32_t mbar) {
    asm volatile(
        "mbarrier.arrive.expect_tx.shared.b64 _, [%0], %1;"
        :: "r"(mbar), "r"((uint32_t)IMG_BYTES) : "memory");
    asm volatile(
        "cp.async.bulk.shared::cluster.global.mbarrier::complete_tx::bytes "
        "[%0], [%1], %2, [%3];"
        :: "r"(dst_smem), "l"(src), "r"((uint32_t)IMG_BYTES), "r"(mbar)
        : "memory");
}

__global__ __launch_bounds__(32) void gather_kernel(
    const float* __restrict__ x, const int* __restrict__ order,
    float* __restrict__ out, int k)
{
    extern __shared__ __align__(128) char dsm[];
    if (threadIdx.x != 0) return;     // single control thread; async engines do the work

    const int base = blockIdx.x * GIPB;
    const int b    = base / k;        // GIPB | k -> all 8 outputs in one batch

    const uint32_t buf0  = (uint32_t)__cvta_generic_to_shared(dsm);
    const uint32_t mbar0 = buf0 + GS * IMG_BYTES;

#pragma unroll
    for (int s = 0; s < GS; s++)
        asm volatile("mbarrier.init.shared.b64 [%0], 1;"
                     :: "r"(mbar0 + s * 8) : "memory");
    asm volatile("fence.proxy.async.shared::cta;" ::: "memory");

    int4 ia = *reinterpret_cast<const int4*>(order + base);
    int4 ib = *reinterpret_cast<const int4*>(order + base + 4);
    int idx[GIPB] = {ia.x, ia.y, ia.z, ia.w, ib.x, ib.y, ib.z, ib.w};

    const size_t row = (size_t)b * NN;

    // prologue: GD loads in flight
#pragma unroll
    for (int j = 0; j < GD; j++)
        bulk_load(buf0 + (j % GS) * IMG_BYTES,
                  x + (row + idx[j]) * IMG_ELEMS,
                  mbar0 + (j % GS) * 8);

#pragma unroll
    for (int j = 0; j < GIPB; j++) {
        const int s = j % GS;
        mbar_wait(mbar0 + s * 8, (j / GS) & 1);

        const float* dst = out + (size_t)(base + j) * IMG_ELEMS;
        asm volatile(
            "cp.async.bulk.global.shared::cta.bulk_group [%0], [%1], %2;"
            :: "l"(dst), "r"(buf0 + s * IMG_BYTES), "r"((uint32_t)IMG_BYTES)
            : "memory");
        asm volatile("cp.async.bulk.commit_group;" ::: "memory");

        const int jn = j + GD;
        if (jn < GIPB) {
            // stage jn%GS last stored at iter jn-GS <= j-2; committed = j+1,
            // pending<=GS-GD => that store's smem read is complete.
            asm volatile("cp.async.bulk.wait_group.read %0;"
                         :: "n"(GS - GD) : "memory");
            bulk_load(buf0 + (jn % GS) * IMG_BYTES,
                      x + (row + idx[jn]) * IMG_ELEMS,
                      mbar0 + (jn % GS) * 8);
        }
    }
    asm volatile("cp.async.bulk.wait_group 0;" ::: "memory");
}

// ---------------------------------------------------------------------------
extern "C" void kernel_launch(void* const* d_in, const int* in_sizes, int n_in,
                              void* d_out, int out_size)
{
    const float* x = (const float*)d_in[0];
    const float* w = (const float*)d_in[1];
    float* out = (float*)d_out;

    const int k = out_size / (BB * IMG_ELEMS);   // = 256

    const int gather_smem = GS * IMG_BYTES + GS * 8;   // 98352 B
    static int attr_set = 0;
    if (!attr_set) {
        cudaFuncSetAttribute(gather_kernel,
                             cudaFuncAttributeMaxDynamicSharedMemorySize,
                             gather_smem);
        attr_set = 1;
    }

    score_kernel<<<(BB * NN) / 8, 256>>>(x, w, g_scores);
    topk_kernel<<<BB, NN>>>(g_scores, g_order, k);
    gather_kernel<<<(BB * 256) / GIPB, 32, gather_smem>>>(x, g_order, out, k);
}